// round 14
// baseline (speedup 1.0000x reference)
#include <cuda_runtime.h>
#include <cuda_bf16.h>
#include <cuda_fp16.h>
#include <cstdint>

#define Bn 16384
#define Tn 24
#define KZX 1056
#define INd 1060
#define G3  384
#define NC  512
#define WS  136

__device__ __align__(16) float g_sc[(size_t)Bn * NC];

__device__ __forceinline__ float sigf(float x){ return __fdividef(1.f, 1.f + __expf(-x)); }
__device__ __forceinline__ float tanha(float x){ return __fdividef(2.f, 1.f + __expf(-2.f*x)) - 1.f; }
__device__ __forceinline__ uint32_t s2u(const void* p){ uint32_t a; asm("{.reg .u64 t; cvta.to.shared.u64 t,%1; cvt.u32.u64 %0,t;}":"=r"(a):"l"(p)); return a; }
__device__ __forceinline__ uint32_t pkhf(float x, float y){ uint32_t d; asm("cvt.rn.f16x2.f32 %0,%1,%2;":"=r"(d):"f"(y),"f"(x)); return d; }
__device__ __forceinline__ float hlo(uint32_t v){ float f; asm("{.reg .b16 l,h; mov.b32 {l,h},%1; cvt.f32.f16 %0,l;}":"=f"(f):"r"(v)); return f; }
__device__ __forceinline__ float hhi(uint32_t v){ float f; asm("{.reg .b16 l,h; mov.b32 {l,h},%1; cvt.f32.f16 %0,h;}":"=f"(f):"r"(v)); return f; }
__device__ __forceinline__ void mmahf(float* c, const uint32_t* a, uint32_t b0, uint32_t b1){
    asm("mma.sync.aligned.m16n8k16.row.col.f32.f16.f16.f32 {%0,%1,%2,%3},{%4,%5,%6,%7},{%8,%9},{%0,%1,%2,%3};"
        : "+f"(c[0]),"+f"(c[1]),"+f"(c[2]),"+f"(c[3])
        : "r"(a[0]),"r"(a[1]),"r"(a[2]),"r"(a[3]),"r"(b0),"r"(b1));
}
__device__ __forceinline__ void ldsm4(uint32_t* r, uint32_t a){
    asm volatile("ldmatrix.sync.aligned.m8n8.x4.shared.b16 {%0,%1,%2,%3},[%4];"
        :"=r"(r[0]),"=r"(r[1]),"=r"(r[2]),"=r"(r[3]):"r"(a));
}

// -------- Phase 1: HMMA fp16 (A hi/lo, W single) GEMM (R13, known-good) --------
#define P1SM 52224
__global__ __launch_bounds__(512,1) void phase1f(
    const float* __restrict__ enc, const float* __restrict__ zin,
    const float* __restrict__ W_ih, const float* __restrict__ b_ih,
    const float* __restrict__ W_dh, const float* __restrict__ b_dh,
    const float* __restrict__ b_hh,
    const float* __restrict__ lobs, const float* __restrict__ sg)
{
    extern __shared__ __align__(1024) char sm[];
    uint32_t sb=s2u(sm);
    const uint32_t oAh=0, oAl=12288, oBh=24576;
    float* colb=(float*)(sm+49152); float* c58=(float*)(sm+50176); float* c59=(float*)(sm+51200);
    int tid=threadIdx.x, lane=tid&31, w=tid>>5;
    int wm=w>>3, wn=w&7;
    int m0=blockIdx.y*128, n0=blockIdx.x*256;

    if(tid<256){
        int j=n0+tid; float cb,w58=0.f,w59=0.f;
        if(j<G3){ cb=b_ih[j]+((j<256)?b_hh[j]:0.f);
                  w58=W_ih[(size_t)j*INd+1058]; w59=W_ih[(size_t)j*INd+1059]; }
        else cb=b_dh[j-G3];
        colb[tid]=cb; c58[tid]=w58; c59[tid]=w59;
    }

    int ra=tid>>2, kq=(tid&3)*4;
    int ma=m0+ra;
    const float* ae=enc+(size_t)ma*1024; const float* az=zin+(size_t)ma*32;
    int jb0=n0+ra, jb1=jb0+128;
    const float* bp0=(jb0<G3)?(W_ih+(size_t)jb0*INd):(W_dh+(size_t)(jb0-G3)*KZX);
    const float* bp1=(jb1<G3)?(W_ih+(size_t)jb1*INd):(W_dh+(size_t)(jb1-G3)*KZX);

    float acc[4][4][4];
    #pragma unroll
    for(int i=0;i<4;i++)
        #pragma unroll
        for(int j2=0;j2<4;j2++){ acc[i][j2][0]=0.f; acc[i][j2][1]=0.f; acc[i][j2][2]=0.f; acc[i][j2][3]=0.f; }

#define CVSTA(off,v) { \
    uint32_t _h0=pkhf((v).x,(v).y), _h1=pkhf((v).z,(v).w); \
    float _rx=(v).x-hlo(_h0), _ry=(v).y-hhi(_h0), _rz=(v).z-hlo(_h1), _rw=(v).w-hhi(_h1); \
    uint32_t _l0=pkhf(_rx,_ry), _l1=pkhf(_rz,_rw); \
    *(uint2*)(sm+oAh+(off))=make_uint2(_h0,_h1); \
    *(uint2*)(sm+oAl+(off))=make_uint2(_l0,_l1); }
#define CVSTB(off,v) { \
    uint32_t _h0=pkhf((v).x,(v).y), _h1=pkhf((v).z,(v).w); \
    *(uint2*)(sm+oBh+(off))=make_uint2(_h0,_h1); }
#define LDT(kt) { int kk=(kt)*16+kq; \
    av=(kk<1024)?*(const float4*)(ae+kk):*(const float4*)(az+(kk-1024)); \
    b0v=*(const float4*)(bp0+kk); b1v=*(const float4*)(bp1+kk); }
#define STT(bf) { \
    CVSTA((bf)*6144+ra*48+(tid&3)*8, av); \
    CVSTB((bf)*12288+ra*48+(tid&3)*8, b0v); \
    CVSTB((bf)*12288+(ra+128)*48+(tid&3)*8, b1v); }

    float4 av,b0v,b1v;
    LDT(0); STT(0);
    __syncthreads();

    for(int kt=0;kt<66;kt++){
        int buf=kt&1;
        if(kt<65) LDT(kt+1);
        uint32_t aBh=sb+oAh+buf*6144+(uint32_t)((wm*64+(lane&15))*48+(lane>>4)*16);
        uint32_t aBl=aBh+(oAl-oAh);
        uint32_t bOff=(uint32_t)((wn*32+(lane>>4)*8+(lane&7))*48+((lane>>3)&1)*16);
        uint32_t bBh=sb+oBh+buf*12288+bOff;
        uint32_t Bh0[4],Bh1[4];
        ldsm4(Bh0,bBh); ldsm4(Bh1,bBh+16*48);
        #pragma unroll
        for(int mt=0;mt<4;mt++){
            uint32_t Af[4],Alf[4];
            ldsm4(Af, aBh+(uint32_t)(mt*16*48));
            ldsm4(Alf,aBl+(uint32_t)(mt*16*48));
            #pragma unroll
            for(int nt=0;nt<4;nt++){
                uint32_t b0=(nt<2?Bh0:Bh1)[(nt&1)*2], b1=(nt<2?Bh0:Bh1)[(nt&1)*2+1];
                mmahf(acc[mt][nt],Af,b0,b1);
                mmahf(acc[mt][nt],Alf,b0,b1);
            }
        }
        __syncthreads();
        if(kt<65){ int nb=(kt+1)&1; STT(nb); }
        __syncthreads();
    }

    const float idt=1.f/4.8f;
    #pragma unroll
    for(int mt=0;mt<4;mt++){
        #pragma unroll
        for(int h=0;h<2;h++){
            int m=m0+wm*64+mt*16+(lane>>2)+8*h;
            float r0=(sg[2*m]-lobs[6*m])*idt, r1=(sg[2*m+1]-lobs[6*m+1])*idt;
            #pragma unroll
            for(int nt=0;nt<4;nt++){
                int jl=wn*32+nt*8+2*(lane&3);
                float vx=acc[mt][nt][2*h]  +colb[jl]  +r0*c58[jl]  +r1*c59[jl];
                float vy=acc[mt][nt][2*h+1]+colb[jl+1]+r0*c58[jl+1]+r1*c59[jl+1];
                *(float2*)&g_sc[(size_t)m*NC+n0+jl]=make_float2(vx,vy);
            }
        }
    }
#undef CVSTA
#undef CVSTB
#undef LDT
#undef STT
}

// -------- Phase 2: 32-row pairs (2-way N split) + 16-row tail pair --------
// 147 blocks x 256 threads (8 warps). Warps 0-5: three pairs, each warp 32 rows
// x half-N, fp32 h-state in regs (cap 256 @ 256thr). Warps 6-7: R11 16-row pair.
// smem: WHs fp16[384*136] @0 (104448), was @104448 (3072), wm4 @107520 (2048),
//       bh2 @109568 (512), hx u32[112][68] @110080 (30464), px @140544 (3584).
#define SM2T 144128
__global__ __launch_bounds__(256,1) void phase2t(
    const float* __restrict__ W_hh, const float* __restrict__ W_ih,
    const float* __restrict__ b_hh,
    const float* __restrict__ W_mu, const float* __restrict__ b_mu,
    const float* __restrict__ W_std, const float* __restrict__ b_std,
    const float* __restrict__ lobs, const float* __restrict__ W_vel,
    const float* __restrict__ b_vel, const float* __restrict__ fut,
    float* __restrict__ out)
{
    extern __shared__ __align__(1024) char sm[];
    __half* WHs=(__half*)sm;
    float2* was=(float2*)(sm+104448);
    float4* wm4=(float4*)(sm+107520);
    float2* bh2=(float2*)(sm+109568);
    uint32_t* hx=(uint32_t*)(sm+110080);
    float2* px=(float2*)(sm+140544);
    int tid=threadIdx.x, lane=tid&31, wid=tid>>5;
    int q=lane&3, rq=lane>>2;
    int rb=blockIdx.x*112;

    for(int i=tid;i<G3*128;i+=256){
        int n=i>>7,k=i&127;
        WHs[n*WS+k]=__float2half(W_hh[i]);
    }
    for(int i=tid;i<G3;i+=256)
        was[i]=make_float2(W_ih[(size_t)i*INd+1056],W_ih[(size_t)i*INd+1057]);
    if(tid<128) wm4[tid]=make_float4(W_mu[tid],W_mu[128+tid],W_std[tid],W_std[128+tid]);
    if(tid<64)  bh2[tid]=make_float2(b_hh[256+2*tid],b_hh[257+2*tid]);
    __syncthreads();

    uint32_t sWH=s2u(WHs);
    uint32_t boff=(uint32_t)(((lane&7)*WS+(lane>>3)*8)*2);
    float bm0=b_mu[0],bm1=b_mu[1],bs0=b_std[0],bs1=b_std[1];

    if(wid<6){
        // ===== 32-row pair path =====
        int p=wid>>1, half=wid&1;
        int rbase=rb+p*32;
        if(rbase>=Bn) return;
        uint32_t hb=(uint32_t)(p*32*68);

        uint32_t Ah[2][8][4];
        float hp[2][32];
        #pragma unroll
        for(int nt=0;nt<2;nt++){
            #pragma unroll
            for(int kt=0;kt<8;kt++)
                #pragma unroll
                for(int rg=0;rg<4;rg++){
                    int r=rbase+nt*16+rq+((rg&1)?8:0);
                    int cb=kt*16+((rg>>1)*8)+2*q;
                    float2 v=*(const float2*)&g_sc[(size_t)r*NC+G3+cb];
                    Ah[nt][kt][rg]=pkhf(v.x,v.y);
                }
            #pragma unroll
            for(int c2=0;c2<8;c2++){
                int cg=half*8+c2;
                int r0=rbase+nt*16+rq;
                float2 v0=*(const float2*)&g_sc[(size_t)r0*NC+G3+8*cg+2*q];
                float2 v1=*(const float2*)&g_sc[(size_t)(r0+8)*NC+G3+8*cg+2*q];
                hp[nt][c2*4+0]=v0.x; hp[nt][c2*4+1]=v0.y;
                hp[nt][c2*4+2]=v1.x; hp[nt][c2*4+3]=v1.y;
            }
        }

        for(int t=0;t<Tn;t++){
            float2 aR0[2],aR1[2];
            if(t==0){
                #pragma unroll
                for(int nt=0;nt<2;nt++){
                    int r0=rbase+nt*16+rq, r1=r0+8;
                    float s0=b_vel[0],s1=b_vel[1],u0=s0,u1=s1;
                    #pragma unroll
                    for(int k=0;k<6;k++){
                        float v0=__ldg(&lobs[r0*6+k]), v1=__ldg(&lobs[r1*6+k]);
                        s0=fmaf(v0,W_vel[k],s0); s1=fmaf(v0,W_vel[6+k],s1);
                        u0=fmaf(v1,W_vel[k],u0); u1=fmaf(v1,W_vel[6+k],u1); }
                    aR0[nt]=make_float2(s0,s1); aR1[nt]=make_float2(u0,u1);
                }
            } else {
                #pragma unroll
                for(int nt=0;nt<2;nt++){
                    int r0=rbase+nt*16+rq;
                    aR0[nt]=*(const float2*)&fut[((size_t)(t-1)*Bn+r0)*6+2];
                    aR1[nt]=*(const float2*)&fut[((size_t)(t-1)*Bn+r0+8)*6+2];
                }
            }
            float p8[2][8];
            #pragma unroll
            for(int nt=0;nt<2;nt++)
                #pragma unroll
                for(int i=0;i<8;i++) p8[nt][i]=0.f;

            #pragma unroll
            for(int c2=0;c2<8;c2++){
                int cg=half*8+c2;
                float cr[2][4],cz[2][4],cn[2][4];
                #pragma unroll
                for(int nt=0;nt<2;nt++)
                    #pragma unroll
                    for(int i=0;i<4;i++){ cr[nt][i]=0.f; cz[nt][i]=0.f; cn[nt][i]=0.f; }
                #pragma unroll
                for(int k2=0;k2<4;k2++){
                    uint32_t ab=(uint32_t)(((8*cg)*WS+k2*32)*2)+boff;
                    uint32_t br[4],bz[4],bn[4];
                    ldsm4(br, sWH+ab);
                    ldsm4(bz, sWH+ab+128*WS*2);
                    ldsm4(bn, sWH+ab+256*WS*2);
                    #pragma unroll
                    for(int h2=0;h2<2;h2++){
                        int kt=2*k2+h2;
                        #pragma unroll
                        for(int nt=0;nt<2;nt++){
                            mmahf(cr[nt],Ah[nt][kt],br[2*h2],br[2*h2+1]);
                            mmahf(cz[nt],Ah[nt][kt],bz[2*h2],bz[2*h2+1]);
                            mmahf(cn[nt],Ah[nt][kt],bn[2*h2],bn[2*h2+1]);
                        }
                    }
                }
                float4 wr=*(const float4*)&was[8*cg+2*q];
                float4 wz=*(const float4*)&was[128+8*cg+2*q];
                float4 wn=*(const float4*)&was[256+8*cg+2*q];
                float2 bh=bh2[4*cg+q];
                float4 w0=wm4[8*cg+2*q], w1=wm4[8*cg+2*q+1];
                #pragma unroll
                for(int nt=0;nt<2;nt++){
                    int r0=rbase+nt*16+rq, r1=r0+8;
                    const float* gp0=&g_sc[(size_t)r0*NC+8*cg+2*q];
                    const float* gp1=&g_sc[(size_t)r1*NC+8*cg+2*q];
                    float2 gr0=*(const float2*)gp0, gz0=*(const float2*)(gp0+128), gn0=*(const float2*)(gp0+256);
                    float2 gr1=*(const float2*)gp1, gz1=*(const float2*)(gp1+128), gn1=*(const float2*)(gp1+256);
                    float r0x=sigf(gr0.x+aR0[nt].x*wr.x+aR0[nt].y*wr.y+cr[nt][0]);
                    float r0y=sigf(gr0.y+aR0[nt].x*wr.z+aR0[nt].y*wr.w+cr[nt][1]);
                    float r1x=sigf(gr1.x+aR1[nt].x*wr.x+aR1[nt].y*wr.y+cr[nt][2]);
                    float r1y=sigf(gr1.y+aR1[nt].x*wr.z+aR1[nt].y*wr.w+cr[nt][3]);
                    float z0x=sigf(gz0.x+aR0[nt].x*wz.x+aR0[nt].y*wz.y+cz[nt][0]);
                    float z0y=sigf(gz0.y+aR0[nt].x*wz.z+aR0[nt].y*wz.w+cz[nt][1]);
                    float z1x=sigf(gz1.x+aR1[nt].x*wz.x+aR1[nt].y*wz.y+cz[nt][2]);
                    float z1y=sigf(gz1.y+aR1[nt].x*wz.z+aR1[nt].y*wz.w+cz[nt][3]);
                    float n0x=tanha(gn0.x+aR0[nt].x*wn.x+aR0[nt].y*wn.y+r0x*(cn[nt][0]+bh.x));
                    float n0y=tanha(gn0.y+aR0[nt].x*wn.z+aR0[nt].y*wn.w+r0y*(cn[nt][1]+bh.y));
                    float n1x=tanha(gn1.x+aR1[nt].x*wn.x+aR1[nt].y*wn.y+r1x*(cn[nt][2]+bh.x));
                    float n1y=tanha(gn1.y+aR1[nt].x*wn.z+aR1[nt].y*wn.w+r1y*(cn[nt][3]+bh.y));
                    float h0x=(1.f-z0x)*n0x+z0x*hp[nt][c2*4+0];
                    float h0y=(1.f-z0y)*n0y+z0y*hp[nt][c2*4+1];
                    float h1x=(1.f-z1x)*n1x+z1x*hp[nt][c2*4+2];
                    float h1y=(1.f-z1y)*n1y+z1y*hp[nt][c2*4+3];
                    hp[nt][c2*4+0]=h0x; hp[nt][c2*4+1]=h0y;
                    hp[nt][c2*4+2]=h1x; hp[nt][c2*4+3]=h1y;
                    p8[nt][0]=fmaf(h0x,w0.x,p8[nt][0]); p8[nt][0]=fmaf(h0y,w1.x,p8[nt][0]);
                    p8[nt][1]=fmaf(h0x,w0.y,p8[nt][1]); p8[nt][1]=fmaf(h0y,w1.y,p8[nt][1]);
                    p8[nt][2]=fmaf(h0x,w0.z,p8[nt][2]); p8[nt][2]=fmaf(h0y,w1.z,p8[nt][2]);
                    p8[nt][3]=fmaf(h0x,w0.w,p8[nt][3]); p8[nt][3]=fmaf(h0y,w1.w,p8[nt][3]);
                    p8[nt][4]=fmaf(h1x,w0.x,p8[nt][4]); p8[nt][4]=fmaf(h1y,w1.x,p8[nt][4]);
                    p8[nt][5]=fmaf(h1x,w0.y,p8[nt][5]); p8[nt][5]=fmaf(h1y,w1.y,p8[nt][5]);
                    p8[nt][6]=fmaf(h1x,w0.z,p8[nt][6]); p8[nt][6]=fmaf(h1y,w1.z,p8[nt][6]);
                    p8[nt][7]=fmaf(h1x,w0.w,p8[nt][7]); p8[nt][7]=fmaf(h1y,w1.w,p8[nt][7]);
                    uint32_t wofs=hb+(uint32_t)((nt*16+rq)*68+cg*4+q);
                    hx[wofs]       =pkhf(h0x,h0y);
                    hx[wofs+8*68]  =pkhf(h1x,h1y);
                }
            }
            #pragma unroll
            for(int nt=0;nt<2;nt++){
                #pragma unroll
                for(int i=0;i<8;i++){
                    p8[nt][i]+=__shfl_xor_sync(~0u,p8[nt][i],1);
                    p8[nt][i]+=__shfl_xor_sync(~0u,p8[nt][i],2);
                }
                float2 mine;
                if(q<2) mine=make_float2((q&1)?p8[nt][4]:p8[nt][0],(q&1)?p8[nt][5]:p8[nt][1]);
                else    mine=make_float2((q&1)?p8[nt][6]:p8[nt][2],(q&1)?p8[nt][7]:p8[nt][3]);
                px[((p*2+nt)*2+half)*32+lane]=mine;
            }
            asm volatile("bar.sync %0,64;"::"r"(p+1):"memory");
            #pragma unroll
            for(int nt=0;nt<2;nt++)
                #pragma unroll
                for(int kt=0;kt<8;kt++)
                    #pragma unroll
                    for(int ch=0;ch<2;ch++){
                        uint32_t pw=hb+(uint32_t)((2*kt+ch)*4+q);
                        Ah[nt][kt][ch*2  ]=hx[pw+(uint32_t)((nt*16+rq)*68)];
                        Ah[nt][kt][ch*2+1]=hx[pw+(uint32_t)((nt*16+rq+8)*68)];
                    }
            if(half==0){
                #pragma unroll
                for(int nt=0;nt<2;nt++){
                    float2 mine=px[((p*2+nt)*2)*32+lane];
                    float2 other=px[((p*2+nt)*2+1)*32+lane];
                    float vx=mine.x+other.x, vy=mine.y+other.y;
                    int orow=rbase+nt*16+rq+((q&1)?8:0);
                    if(q<2)
                        *(float2*)&out[(size_t)t*Bn*2+(size_t)orow*2]=make_float2(vx+bm0,vy+bm1);
                    else
                        *(float2*)&out[(size_t)(Tn+t)*Bn*2+(size_t)orow*2]=
                            make_float2(__expf(0.5f*(vx+bs0)),__expf(0.5f*(vy+bs1)));
                }
            }
            asm volatile("bar.sync %0,64;"::"r"(p+1):"memory");
        }
    } else {
        // ===== 16-row tail pair (R11 verbatim), rows rb+96..rb+111 =====
        int half=wid&1;
        int rbase=rb+96;
        if(rbase>=Bn) return;
        int row0=rbase+rq, row1=row0+8;
        uint32_t hb=(uint32_t)(96*68);

        uint32_t Ah[8][4];
        float hp[32];
        #pragma unroll
        for(int kt=0;kt<8;kt++)
            #pragma unroll
            for(int rg=0;rg<4;rg++){
                int r=(rg&1)?row1:row0;
                int cb=kt*16+((rg>>1)*8)+2*q;
                float2 v=*(const float2*)&g_sc[(size_t)r*NC+G3+cb];
                Ah[kt][rg]=pkhf(v.x,v.y);
            }
        #pragma unroll
        for(int c2=0;c2<8;c2++){
            int cg=half*8+c2;
            float2 v0=*(const float2*)&g_sc[(size_t)row0*NC+G3+8*cg+2*q];
            float2 v1=*(const float2*)&g_sc[(size_t)row1*NC+G3+8*cg+2*q];
            hp[c2*4+0]=v0.x; hp[c2*4+1]=v0.y;
            hp[c2*4+2]=v1.x; hp[c2*4+3]=v1.y;
        }
        for(int t=0;t<Tn;t++){
            float2 aR0,aR1;
            if(t==0){
                float s0=b_vel[0],s1=b_vel[1],t0=s0,t1=s1;
                #pragma unroll
                for(int k=0;k<6;k++){
                    float v0=__ldg(&lobs[row0*6+k]), v1=__ldg(&lobs[row1*6+k]);
                    s0=fmaf(v0,W_vel[k],s0); s1=fmaf(v0,W_vel[6+k],s1);
                    t0=fmaf(v1,W_vel[k],t0); t1=fmaf(v1,W_vel[6+k],t1); }
                aR0=make_float2(s0,s1); aR1=make_float2(t0,t1);
            } else {
                aR0=*(const float2*)&fut[((size_t)(t-1)*Bn+row0)*6+2];
                aR1=*(const float2*)&fut[((size_t)(t-1)*Bn+row1)*6+2];
            }
            float p0=0,p1=0,p2=0,p3=0,p4=0,p5=0,p6=0,p7=0;
            #pragma unroll
            for(int c2=0;c2<8;c2++){
                int cg=half*8+c2;
                const float* gp0=&g_sc[(size_t)row0*NC+8*cg+2*q];
                const float* gp1=&g_sc[(size_t)row1*NC+8*cg+2*q];
                float2 gr0=*(const float2*)gp0, gz0=*(const float2*)(gp0+128), gn0=*(const float2*)(gp0+256);
                float2 gr1=*(const float2*)gp1, gz1=*(const float2*)(gp1+128), gn1=*(const float2*)(gp1+256);
                float cr[4]={0,0,0,0}, cz[4]={0,0,0,0}, cn[4]={0,0,0,0};
                #pragma unroll
                for(int k2=0;k2<4;k2++){
                    uint32_t ab=(uint32_t)(((8*cg)*WS+k2*32)*2)+boff;
                    uint32_t br[4],bz[4],bn[4];
                    ldsm4(br, sWH+ab);
                    ldsm4(bz, sWH+ab+128*WS*2);
                    ldsm4(bn, sWH+ab+256*WS*2);
                    #pragma unroll
                    for(int h2=0;h2<2;h2++){
                        int kt=2*k2+h2;
                        mmahf(cr,Ah[kt],br[2*h2],br[2*h2+1]);
                        mmahf(cz,Ah[kt],bz[2*h2],bz[2*h2+1]);
                        mmahf(cn,Ah[kt],bn[2*h2],bn[2*h2+1]);
                    }
                }
                float4 wr=*(const float4*)&was[8*cg+2*q];
                float4 wz=*(const float4*)&was[128+8*cg+2*q];
                float4 wn=*(const float4*)&was[256+8*cg+2*q];
                float2 bh=bh2[4*cg+q];
                float4 w0=wm4[8*cg+2*q], w1=wm4[8*cg+2*q+1];
                float r0x=sigf(gr0.x+aR0.x*wr.x+aR0.y*wr.y+cr[0]);
                float r0y=sigf(gr0.y+aR0.x*wr.z+aR0.y*wr.w+cr[1]);
                float r1x=sigf(gr1.x+aR1.x*wr.x+aR1.y*wr.y+cr[2]);
                float r1y=sigf(gr1.y+aR1.x*wr.z+aR1.y*wr.w+cr[3]);
                float z0x=sigf(gz0.x+aR0.x*wz.x+aR0.y*wz.y+cz[0]);
                float z0y=sigf(gz0.y+aR0.x*wz.z+aR0.y*wz.w+cz[1]);
                float z1x=sigf(gz1.x+aR1.x*wz.x+aR1.y*wz.y+cz[2]);
                float z1y=sigf(gz1.y+aR1.x*wz.z+aR1.y*wz.w+cz[3]);
                float n0x=tanha(gn0.x+aR0.x*wn.x+aR0.y*wn.y+r0x*(cn[0]+bh.x));
                float n0y=tanha(gn0.y+aR0.x*wn.z+aR0.y*wn.w+r0y*(cn[1]+bh.y));
                float n1x=tanha(gn1.x+aR1.x*wn.x+aR1.y*wn.y+r1x*(cn[2]+bh.x));
                float n1y=tanha(gn1.y+aR1.x*wn.z+aR1.y*wn.w+r1y*(cn[3]+bh.y));
                float h0x=(1.f-z0x)*n0x+z0x*hp[c2*4+0];
                float h0y=(1.f-z0y)*n0y+z0y*hp[c2*4+1];
                float h1x=(1.f-z1x)*n1x+z1x*hp[c2*4+2];
                float h1y=(1.f-z1y)*n1y+z1y*hp[c2*4+3];
                hp[c2*4+0]=h0x; hp[c2*4+1]=h0y;
                hp[c2*4+2]=h1x; hp[c2*4+3]=h1y;
                p0=fmaf(h0x,w0.x,p0); p0=fmaf(h0y,w1.x,p0);
                p1=fmaf(h0x,w0.y,p1); p1=fmaf(h0y,w1.y,p1);
                p2=fmaf(h0x,w0.z,p2); p2=fmaf(h0y,w1.z,p2);
                p3=fmaf(h0x,w0.w,p3); p3=fmaf(h0y,w1.w,p3);
                p4=fmaf(h1x,w0.x,p4); p4=fmaf(h1y,w1.x,p4);
                p5=fmaf(h1x,w0.y,p5); p5=fmaf(h1y,w1.y,p5);
                p6=fmaf(h1x,w0.z,p6); p6=fmaf(h1y,w1.z,p6);
                p7=fmaf(h1x,w0.w,p7); p7=fmaf(h1y,w1.w,p7);
                uint32_t wofs=hb+(uint32_t)(rq*68+cg*4+q);
                hx[wofs]      =pkhf(h0x,h0y);
                hx[wofs+8*68] =pkhf(h1x,h1y);
            }
            p0+=__shfl_xor_sync(~0u,p0,1); p0+=__shfl_xor_sync(~0u,p0,2);
            p1+=__shfl_xor_sync(~0u,p1,1); p1+=__shfl_xor_sync(~0u,p1,2);
            p2+=__shfl_xor_sync(~0u,p2,1); p2+=__shfl_xor_sync(~0u,p2,2);
            p3+=__shfl_xor_sync(~0u,p3,1); p3+=__shfl_xor_sync(~0u,p3,2);
            p4+=__shfl_xor_sync(~0u,p4,1); p4+=__shfl_xor_sync(~0u,p4,2);
            p5+=__shfl_xor_sync(~0u,p5,1); p5+=__shfl_xor_sync(~0u,p5,2);
            p6+=__shfl_xor_sync(~0u,p6,1); p6+=__shfl_xor_sync(~0u,p6,2);
            p7+=__shfl_xor_sync(~0u,p7,1); p7+=__shfl_xor_sync(~0u,p7,2);
            float2 mine;
            if(q<2) mine=make_float2((q&1)?p4:p0,(q&1)?p5:p1);
            else    mine=make_float2((q&1)?p6:p2,(q&1)?p7:p3);
            px[(12+half)*32+lane]=mine;
            asm volatile("bar.sync 4,64;":::"memory");
            #pragma unroll
            for(int kt=0;kt<8;kt++)
                #pragma unroll
                for(int ch=0;ch<2;ch++){
                    uint32_t pw=hb+(uint32_t)((2*kt+ch)*4+q);
                    Ah[kt][ch*2  ]=hx[pw+rq*68];
                    Ah[kt][ch*2+1]=hx[pw+(rq+8)*68];
                }
            if(half==0){
                float2 other=px[13*32+lane];
                float vx=mine.x+other.x, vy=mine.y+other.y;
                int orow=(q&1)?row1:row0;
                if(q<2)
                    *(float2*)&out[(size_t)t*Bn*2+(size_t)orow*2]=make_float2(vx+bm0,vy+bm1);
                else
                    *(float2*)&out[(size_t)(Tn+t)*Bn*2+(size_t)orow*2]=
                        make_float2(__expf(0.5f*(vx+bs0)),__expf(0.5f*(vy+bs1)));
            }
            asm volatile("bar.sync 4,64;":::"memory");
        }
    }
}

extern "C" void kernel_launch(void* const* d_in, const int* in_sizes, int n_in,
                              void* d_out, int out_size) {
    const float* lobs=(const float*)d_in[0];
    const float* enc =(const float*)d_in[1];
    const float* zin =(const float*)d_in[2];
    const float* sg  =(const float*)d_in[3];
    const float* fut =(const float*)d_in[4];
    const float* W_dh=(const float*)d_in[5];
    const float* b_dh=(const float*)d_in[6];
    const float* W_vel=(const float*)d_in[7];
    const float* b_vel=(const float*)d_in[8];
    const float* W_ih=(const float*)d_in[9];
    const float* b_ih=(const float*)d_in[10];
    const float* W_hh=(const float*)d_in[11];
    const float* b_hh=(const float*)d_in[12];
    const float* W_mu=(const float*)d_in[13];
    const float* b_mu=(const float*)d_in[14];
    const float* W_std=(const float*)d_in[15];
    const float* b_std=(const float*)d_in[16];
    float* out=(float*)d_out;

    cudaFuncSetAttribute(phase1f, cudaFuncAttributeMaxDynamicSharedMemorySize, P1SM);
    phase1f<<<dim3(2,128),512,P1SM>>>(enc,zin,W_ih,b_ih,W_dh,b_dh,b_hh,lobs,sg);

    cudaFuncSetAttribute(phase2t, cudaFuncAttributeMaxDynamicSharedMemorySize, SM2T);
    phase2t<<<147,256,SM2T>>>(W_hh,W_ih,b_hh,W_mu,b_mu,W_std,b_std,
                              lobs,W_vel,b_vel,fut,out);
}

// round 15
// speedup vs baseline: 1.0887x; 1.0887x over previous
#include <cuda_runtime.h>
#include <cuda_bf16.h>
#include <cuda_fp16.h>
#include <cstdint>

#define Bn 16384
#define Tn 24
#define KZX 1056
#define INd 1060
#define G3  384
#define NC  512
#define WS  136

__device__ __align__(16) float g_sc[(size_t)Bn * NC];
__device__ __align__(16) __half g_wh[(size_t)512 * KZX];

__device__ __forceinline__ float sigf(float x){ return __fdividef(1.f, 1.f + __expf(-x)); }
__device__ __forceinline__ float tanha(float x){ return __fdividef(2.f, 1.f + __expf(-2.f*x)) - 1.f; }
__device__ __forceinline__ uint32_t s2u(const void* p){ uint32_t a; asm("{.reg .u64 t; cvta.to.shared.u64 t,%1; cvt.u32.u64 %0,t;}":"=r"(a):"l"(p)); return a; }
__device__ __forceinline__ uint32_t pkhf(float x, float y){ uint32_t d; asm("cvt.rn.f16x2.f32 %0,%1,%2;":"=r"(d):"f"(y),"f"(x)); return d; }
__device__ __forceinline__ float hlo(uint32_t v){ float f; asm("{.reg .b16 l,h; mov.b32 {l,h},%1; cvt.f32.f16 %0,l;}":"=f"(f):"r"(v)); return f; }
__device__ __forceinline__ float hhi(uint32_t v){ float f; asm("{.reg .b16 l,h; mov.b32 {l,h},%1; cvt.f32.f16 %0,h;}":"=f"(f):"r"(v)); return f; }
__device__ __forceinline__ void mmahf(float* c, const uint32_t* a, uint32_t b0, uint32_t b1){
    asm("mma.sync.aligned.m16n8k16.row.col.f32.f16.f16.f32 {%0,%1,%2,%3},{%4,%5,%6,%7},{%8,%9},{%0,%1,%2,%3};"
        : "+f"(c[0]),"+f"(c[1]),"+f"(c[2]),"+f"(c[3])
        : "r"(a[0]),"r"(a[1]),"r"(a[2]),"r"(a[3]),"r"(b0),"r"(b1));
}
__device__ __forceinline__ void ldsm4(uint32_t* r, uint32_t a){
    asm volatile("ldmatrix.sync.aligned.m8n8.x4.shared.b16 {%0,%1,%2,%3},[%4];"
        :"=r"(r[0]),"=r"(r[1]),"=r"(r[2]),"=r"(r[3]):"r"(a));
}

// -------- Prep: convert [W_ih[:, :1056] ; W_dh] to fp16 once --------
__global__ void convW(const float* __restrict__ W_ih, const float* __restrict__ W_dh){
    int i = blockIdx.x*256 + threadIdx.x;
    if(i >= 512*KZX) return;
    int row = i / KZX, k = i - row*KZX;
    float v = (row < G3) ? W_ih[(size_t)row*INd + k] : W_dh[(size_t)(row-G3)*KZX + k];
    g_wh[i] = __float2half(v);
}

// -------- Phase 1: HMMA fp16 (A hi/lo fused, W preconverted), single sync ------
#define P1SM 52224
__global__ __launch_bounds__(512,1) void phase1f(
    const float* __restrict__ enc, const float* __restrict__ zin,
    const float* __restrict__ W_ih, const float* __restrict__ b_ih,
    const float* __restrict__ b_dh, const float* __restrict__ b_hh,
    const float* __restrict__ lobs, const float* __restrict__ sg)
{
    extern __shared__ __align__(1024) char sm[];
    uint32_t sb=s2u(sm);
    const uint32_t oAh=0, oAl=12288, oBh=24576;
    float* colb=(float*)(sm+49152); float* c58=(float*)(sm+50176); float* c59=(float*)(sm+51200);
    int tid=threadIdx.x, lane=tid&31, w=tid>>5;
    int wm=w>>3, wn=w&7;
    int m0=blockIdx.y*128, n0=blockIdx.x*256;

    if(tid<256){
        int j=n0+tid; float cb,w58=0.f,w59=0.f;
        if(j<G3){ cb=b_ih[j]+((j<256)?b_hh[j]:0.f);
                  w58=W_ih[(size_t)j*INd+1058]; w59=W_ih[(size_t)j*INd+1059]; }
        else cb=b_dh[j-G3];
        colb[tid]=cb; c58[tid]=w58; c59[tid]=w59;
    }

    int ra=tid>>2, kq=(tid&3)*4;
    int ma=m0+ra;
    const float* ae=enc+(size_t)ma*1024; const float* az=zin+(size_t)ma*32;
    const __half* bp0h=g_wh+(size_t)(n0+ra)*KZX;
    const __half* bp1h=bp0h+(size_t)128*KZX;

    float acc[4][4][4];
    #pragma unroll
    for(int i=0;i<4;i++)
        #pragma unroll
        for(int j2=0;j2<4;j2++){ acc[i][j2][0]=0.f; acc[i][j2][1]=0.f; acc[i][j2][2]=0.f; acc[i][j2][3]=0.f; }

#define LDT(kt) { int kk=(kt)*16+kq; \
    av=(kk<1024)?*(const float4*)(ae+kk):*(const float4*)(az+(kk-1024)); \
    bh0=*(const uint2*)(bp0h+kk); bh1=*(const uint2*)(bp1h+kk); }
#define STT(bf) { \
    uint32_t _off=(bf)*6144+ra*48+(tid&3)*8; \
    uint32_t _h0=pkhf(av.x,av.y), _h1=pkhf(av.z,av.w); \
    float _rx=av.x-hlo(_h0), _ry=av.y-hhi(_h0), _rz=av.z-hlo(_h1), _rw=av.w-hhi(_h1); \
    *(uint2*)(sm+oAh+_off)=make_uint2(_h0,_h1); \
    *(uint2*)(sm+oAl+_off)=make_uint2(pkhf(_rx,_ry),pkhf(_rz,_rw)); \
    *(uint2*)(sm+oBh+(bf)*12288+ra*48+(tid&3)*8)=bh0; \
    *(uint2*)(sm+oBh+(bf)*12288+(ra+128)*48+(tid&3)*8)=bh1; }

    float4 av; uint2 bh0,bh1;
    LDT(0); STT(0);
    __syncthreads();

    for(int kt=0;kt<66;kt++){
        int buf=kt&1;
        if(kt<65) LDT(kt+1);
        uint32_t aBh=sb+oAh+buf*6144+(uint32_t)((wm*64+(lane&15))*48+(lane>>4)*16);
        uint32_t aBl=aBh+(oAl-oAh);
        uint32_t bOff=(uint32_t)((wn*32+(lane>>4)*8+(lane&7))*48+((lane>>3)&1)*16);
        uint32_t bBh=sb+oBh+buf*12288+bOff;
        uint32_t Bh0[4],Bh1[4];
        ldsm4(Bh0,bBh); ldsm4(Bh1,bBh+16*48);
        #pragma unroll
        for(int mt=0;mt<4;mt++){
            uint32_t Af[4],Alf[4];
            ldsm4(Af, aBh+(uint32_t)(mt*16*48));
            ldsm4(Alf,aBl+(uint32_t)(mt*16*48));
            #pragma unroll
            for(int nt=0;nt<4;nt++){
                uint32_t b0=(nt<2?Bh0:Bh1)[(nt&1)*2], b1=(nt<2?Bh0:Bh1)[(nt&1)*2+1];
                mmahf(acc[mt][nt],Af,b0,b1);
                mmahf(acc[mt][nt],Alf,b0,b1);
            }
        }
        if(kt<65){ int nb=(kt+1)&1; STT(nb); }
        __syncthreads();
    }

    const float idt=1.f/4.8f;
    #pragma unroll
    for(int mt=0;mt<4;mt++){
        #pragma unroll
        for(int h=0;h<2;h++){
            int m=m0+wm*64+mt*16+(lane>>2)+8*h;
            float r0=(sg[2*m]-lobs[6*m])*idt, r1=(sg[2*m+1]-lobs[6*m+1])*idt;
            #pragma unroll
            for(int nt=0;nt<4;nt++){
                int jl=wn*32+nt*8+2*(lane&3);
                float vx=acc[mt][nt][2*h]  +colb[jl]  +r0*c58[jl]  +r1*c59[jl];
                float vy=acc[mt][nt][2*h+1]+colb[jl+1]+r0*c58[jl+1]+r1*c59[jl+1];
                *(float2*)&g_sc[(size_t)m*NC+n0+jl]=make_float2(vx,vy);
            }
        }
    }
#undef LDT
#undef STT
}

// -------- Phase 2: 14-warp pairs + single-product fp16 + fp32 h-state --------
// (R11/R13 phase2r, verbatim — known good at 225us)
#define SM2R 144128
__global__ __launch_bounds__(448,1) void phase2r(
    const float* __restrict__ W_hh, const float* __restrict__ W_ih,
    const float* __restrict__ b_hh,
    const float* __restrict__ W_mu, const float* __restrict__ b_mu,
    const float* __restrict__ W_std, const float* __restrict__ b_std,
    const float* __restrict__ lobs, const float* __restrict__ W_vel,
    const float* __restrict__ b_vel, const float* __restrict__ fut,
    float* __restrict__ out)
{
    extern __shared__ __align__(1024) char sm[];
    __half* WHs=(__half*)sm;
    float2* was=(float2*)(sm+104448);
    float4* wm4=(float4*)(sm+107520);
    float2* bh2=(float2*)(sm+109568);
    uint32_t* hx=(uint32_t*)(sm+110080);
    float2* px=(float2*)(sm+140544);
    int tid=threadIdx.x, lane=tid&31, wid=tid>>5;
    int pair=wid>>1, half=wid&1;
    int q=lane&3, rq=lane>>2;
    int rb=blockIdx.x*112+pair*16;
    int row0=rb+rq, row1=row0+8;
    bool active=rb<Bn;

    for(int i=tid;i<G3*128;i+=448){
        int n=i>>7,k=i&127;
        WHs[n*WS+k]=__float2half(W_hh[i]);
    }
    for(int i=tid;i<G3;i+=448)
        was[i]=make_float2(W_ih[(size_t)i*INd+1056],W_ih[(size_t)i*INd+1057]);
    if(tid<128) wm4[tid]=make_float4(W_mu[tid],W_mu[128+tid],W_std[tid],W_std[128+tid]);
    if(tid<64)  bh2[tid]=make_float2(b_hh[256+2*tid],b_hh[257+2*tid]);
    __syncthreads();
    if(!active) return;

    uint32_t sWH=s2u(WHs);
    uint32_t boff=(uint32_t)(((lane&7)*WS+(lane>>3)*8)*2);
    uint32_t hb=(uint32_t)(pair*1088);

    uint32_t Ah[8][4];
    float hp[32];
    #pragma unroll
    for(int kt=0;kt<8;kt++){
        #pragma unroll
        for(int rg=0;rg<4;rg++){
            int r=(rg&1)?row1:row0;
            int cb=kt*16+((rg>>1)*8)+2*q;
            float2 v=*(const float2*)&g_sc[(size_t)r*NC+G3+cb];
            Ah[kt][rg]=pkhf(v.x,v.y);
        }
    }
    #pragma unroll
    for(int c2=0;c2<8;c2++){
        int cg=half*8+c2;
        float2 v0=*(const float2*)&g_sc[(size_t)row0*NC+G3+8*cg+2*q];
        float2 v1=*(const float2*)&g_sc[(size_t)row1*NC+G3+8*cg+2*q];
        hp[c2*4+0]=v0.x; hp[c2*4+1]=v0.y;
        hp[c2*4+2]=v1.x; hp[c2*4+3]=v1.y;
    }
    float2 a0r0,a0r1;
    { float s0=b_vel[0],s1=b_vel[1],t0=s0,t1=s1;
      #pragma unroll
      for(int k=0;k<6;k++){
          float v0=__ldg(&lobs[row0*6+k]), v1=__ldg(&lobs[row1*6+k]);
          s0=fmaf(v0,W_vel[k],s0); s1=fmaf(v0,W_vel[6+k],s1);
          t0=fmaf(v1,W_vel[k],t0); t1=fmaf(v1,W_vel[6+k],t1); }
      a0r0=make_float2(s0,s1); a0r1=make_float2(t0,t1); }
    float bm0=b_mu[0],bm1=b_mu[1],bs0=b_std[0],bs1=b_std[1];

    for(int t=0;t<Tn;t++){
        float2 aR0,aR1;
        if(t==0){ aR0=a0r0; aR1=a0r1; }
        else { aR0=*(const float2*)&fut[((size_t)(t-1)*Bn+row0)*6+2];
               aR1=*(const float2*)&fut[((size_t)(t-1)*Bn+row1)*6+2]; }
        float p0=0,p1=0,p2=0,p3=0,p4=0,p5=0,p6=0,p7=0;
        #pragma unroll
        for(int c2=0;c2<8;c2++){
            int cg=half*8+c2;
            const float* gp0=&g_sc[(size_t)row0*NC+8*cg+2*q];
            const float* gp1=&g_sc[(size_t)row1*NC+8*cg+2*q];
            float2 gr0=*(const float2*)gp0, gz0=*(const float2*)(gp0+128), gn0=*(const float2*)(gp0+256);
            float2 gr1=*(const float2*)gp1, gz1=*(const float2*)(gp1+128), gn1=*(const float2*)(gp1+256);
            float cr[4]={0,0,0,0}, cz[4]={0,0,0,0}, cn[4]={0,0,0,0};
            #pragma unroll
            for(int k2=0;k2<4;k2++){
                uint32_t ab=(uint32_t)(((8*cg)*WS+k2*32)*2)+boff;
                uint32_t br[4],bz[4],bn[4];
                ldsm4(br, sWH+ab);
                ldsm4(bz, sWH+ab+128*WS*2);
                ldsm4(bn, sWH+ab+256*WS*2);
                #pragma unroll
                for(int h2=0;h2<2;h2++){
                    int kt=2*k2+h2;
                    mmahf(cr,Ah[kt],br[2*h2],br[2*h2+1]);
                    mmahf(cz,Ah[kt],bz[2*h2],bz[2*h2+1]);
                    mmahf(cn,Ah[kt],bn[2*h2],bn[2*h2+1]);
                }
            }
            float4 wr=*(const float4*)&was[8*cg+2*q];
            float4 wz=*(const float4*)&was[128+8*cg+2*q];
            float4 wn=*(const float4*)&was[256+8*cg+2*q];
            float2 bh=bh2[4*cg+q];
            float4 w0=wm4[8*cg+2*q], w1=wm4[8*cg+2*q+1];
            float r0x=sigf(gr0.x+aR0.x*wr.x+aR0.y*wr.y+cr[0]);
            float r0y=sigf(gr0.y+aR0.x*wr.z+aR0.y*wr.w+cr[1]);
            float r1x=sigf(gr1.x+aR1.x*wr.x+aR1.y*wr.y+cr[2]);
            float r1y=sigf(gr1.y+aR1.x*wr.z+aR1.y*wr.w+cr[3]);
            float z0x=sigf(gz0.x+aR0.x*wz.x+aR0.y*wz.y+cz[0]);
            float z0y=sigf(gz0.y+aR0.x*wz.z+aR0.y*wz.w+cz[1]);
            float z1x=sigf(gz1.x+aR1.x*wz.x+aR1.y*wz.y+cz[2]);
            float z1y=sigf(gz1.y+aR1.x*wz.z+aR1.y*wz.w+cz[3]);
            float n0x=tanha(gn0.x+aR0.x*wn.x+aR0.y*wn.y+r0x*(cn[0]+bh.x));
            float n0y=tanha(gn0.y+aR0.x*wn.z+aR0.y*wn.w+r0y*(cn[1]+bh.y));
            float n1x=tanha(gn1.x+aR1.x*wn.x+aR1.y*wn.y+r1x*(cn[2]+bh.x));
            float n1y=tanha(gn1.y+aR1.x*wn.z+aR1.y*wn.w+r1y*(cn[3]+bh.y));
            float h0x=(1.f-z0x)*n0x+z0x*hp[c2*4+0];
            float h0y=(1.f-z0y)*n0y+z0y*hp[c2*4+1];
            float h1x=(1.f-z1x)*n1x+z1x*hp[c2*4+2];
            float h1y=(1.f-z1y)*n1y+z1y*hp[c2*4+3];
            hp[c2*4+0]=h0x; hp[c2*4+1]=h0y;
            hp[c2*4+2]=h1x; hp[c2*4+3]=h1y;
            p0=fmaf(h0x,w0.x,p0); p0=fmaf(h0y,w1.x,p0);
            p1=fmaf(h0x,w0.y,p1); p1=fmaf(h0y,w1.y,p1);
            p2=fmaf(h0x,w0.z,p2); p2=fmaf(h0y,w1.z,p2);
            p3=fmaf(h0x,w0.w,p3); p3=fmaf(h0y,w1.w,p3);
            p4=fmaf(h1x,w0.x,p4); p4=fmaf(h1y,w1.x,p4);
            p5=fmaf(h1x,w0.y,p5); p5=fmaf(h1y,w1.y,p5);
            p6=fmaf(h1x,w0.z,p6); p6=fmaf(h1y,w1.z,p6);
            p7=fmaf(h1x,w0.w,p7); p7=fmaf(h1y,w1.w,p7);
            uint32_t wofs=hb+(uint32_t)(cg*4+q);
            hx[wofs+rq*68]    =pkhf(h0x,h0y);
            hx[wofs+(rq+8)*68]=pkhf(h1x,h1y);
        }
        p0+=__shfl_xor_sync(~0u,p0,1); p0+=__shfl_xor_sync(~0u,p0,2);
        p1+=__shfl_xor_sync(~0u,p1,1); p1+=__shfl_xor_sync(~0u,p1,2);
        p2+=__shfl_xor_sync(~0u,p2,1); p2+=__shfl_xor_sync(~0u,p2,2);
        p3+=__shfl_xor_sync(~0u,p3,1); p3+=__shfl_xor_sync(~0u,p3,2);
        p4+=__shfl_xor_sync(~0u,p4,1); p4+=__shfl_xor_sync(~0u,p4,2);
        p5+=__shfl_xor_sync(~0u,p5,1); p5+=__shfl_xor_sync(~0u,p5,2);
        p6+=__shfl_xor_sync(~0u,p6,1); p6+=__shfl_xor_sync(~0u,p6,2);
        p7+=__shfl_xor_sync(~0u,p7,1); p7+=__shfl_xor_sync(~0u,p7,2);
        float2 mine;
        if(q<2) mine=make_float2((q&1)?p4:p0,(q&1)?p5:p1);
        else    mine=make_float2((q&1)?p6:p2,(q&1)?p7:p3);
        px[pair*64+half*32+lane]=mine;
        asm volatile("bar.sync %0,64;"::"r"(pair+1):"memory");
        #pragma unroll
        for(int kt=0;kt<8;kt++){
            #pragma unroll
            for(int ch=0;ch<2;ch++){
                uint32_t pw=hb+(uint32_t)((2*kt+ch)*4+q);
                Ah[kt][ch*2  ]=hx[pw+rq*68];
                Ah[kt][ch*2+1]=hx[pw+(rq+8)*68];
            }
        }
        if(half==0){
            float2 other=px[pair*64+32+lane];
            float vx=mine.x+other.x, vy=mine.y+other.y;
            int orow=(q&1)?row1:row0;
            if(q<2)
                *(float2*)&out[(size_t)t*Bn*2+(size_t)orow*2]=make_float2(vx+bm0,vy+bm1);
            else
                *(float2*)&out[(size_t)(Tn+t)*Bn*2+(size_t)orow*2]=
                    make_float2(__expf(0.5f*(vx+bs0)),__expf(0.5f*(vy+bs1)));
        }
        asm volatile("bar.sync %0,64;"::"r"(pair+1):"memory");
    }
}

extern "C" void kernel_launch(void* const* d_in, const int* in_sizes, int n_in,
                              void* d_out, int out_size) {
    const float* lobs=(const float*)d_in[0];
    const float* enc =(const float*)d_in[1];
    const float* zin =(const float*)d_in[2];
    const float* sg  =(const float*)d_in[3];
    const float* fut =(const float*)d_in[4];
    const float* W_dh=(const float*)d_in[5];
    const float* b_dh=(const float*)d_in[6];
    const float* W_vel=(const float*)d_in[7];
    const float* b_vel=(const float*)d_in[8];
    const float* W_ih=(const float*)d_in[9];
    const float* b_ih=(const float*)d_in[10];
    const float* W_hh=(const float*)d_in[11];
    const float* b_hh=(const float*)d_in[12];
    const float* W_mu=(const float*)d_in[13];
    const float* b_mu=(const float*)d_in[14];
    const float* W_std=(const float*)d_in[15];
    const float* b_std=(const float*)d_in[16];
    float* out=(float*)d_out;

    convW<<<(512*KZX+255)/256,256>>>(W_ih,W_dh);

    cudaFuncSetAttribute(phase1f, cudaFuncAttributeMaxDynamicSharedMemorySize, P1SM);
    phase1f<<<dim3(2,128),512,P1SM>>>(enc,zin,W_ih,b_ih,b_dh,b_hh,lobs,sg);

    cudaFuncSetAttribute(phase2r, cudaFuncAttributeMaxDynamicSharedMemorySize, SM2R);
    phase2r<<<147,448,SM2R>>>(W_hh,W_ih,b_hh,W_mu,b_mu,W_std,b_std,
                              lobs,W_vel,b_vel,fut,out);
}

// round 16
// speedup vs baseline: 1.1831x; 1.0868x over previous
#include <cuda_runtime.h>
#include <cuda_bf16.h>
#include <cuda_fp16.h>
#include <cstdint>

#define Bn 16384
#define Tn 24
#define KZX 1056
#define INd 1060
#define G3  384
#define NC  512
#define WS  136

__device__ __align__(16) float g_sc[(size_t)Bn * NC];
__device__ __align__(16) __half g_wh[(size_t)512 * KZX];

__device__ __forceinline__ float sigf(float x){ return __fdividef(1.f, 1.f + __expf(-x)); }
__device__ __forceinline__ float tanha(float x){ return __fdividef(2.f, 1.f + __expf(-2.f*x)) - 1.f; }
__device__ __forceinline__ uint32_t s2u(const void* p){ uint32_t a; asm("{.reg .u64 t; cvta.to.shared.u64 t,%1; cvt.u32.u64 %0,t;}":"=r"(a):"l"(p)); return a; }
__device__ __forceinline__ uint32_t pkhf(float x, float y){ uint32_t d; asm("cvt.rn.f16x2.f32 %0,%1,%2;":"=r"(d):"f"(y),"f"(x)); return d; }
__device__ __forceinline__ float hlo(uint32_t v){ float f; asm("{.reg .b16 l,h; mov.b32 {l,h},%1; cvt.f32.f16 %0,l;}":"=f"(f):"r"(v)); return f; }
__device__ __forceinline__ float hhi(uint32_t v){ float f; asm("{.reg .b16 l,h; mov.b32 {l,h},%1; cvt.f32.f16 %0,h;}":"=f"(f):"r"(v)); return f; }
__device__ __forceinline__ void mmahf(float* c, const uint32_t* a, uint32_t b0, uint32_t b1){
    asm("mma.sync.aligned.m16n8k16.row.col.f32.f16.f16.f32 {%0,%1,%2,%3},{%4,%5,%6,%7},{%8,%9},{%0,%1,%2,%3};"
        : "+f"(c[0]),"+f"(c[1]),"+f"(c[2]),"+f"(c[3])
        : "r"(a[0]),"r"(a[1]),"r"(a[2]),"r"(a[3]),"r"(b0),"r"(b1));
}
__device__ __forceinline__ void ldsm4(uint32_t* r, uint32_t a){
    asm volatile("ldmatrix.sync.aligned.m8n8.x4.shared.b16 {%0,%1,%2,%3},[%4];"
        :"=r"(r[0]),"=r"(r[1]),"=r"(r[2]),"=r"(r[3]):"r"(a));
}

// -------- Prep: convert [W_ih[:, :1056] ; W_dh] to fp16 once --------
__global__ void convW(const float* __restrict__ W_ih, const float* __restrict__ W_dh){
    int i = blockIdx.x*256 + threadIdx.x;
    if(i >= 512*KZX) return;
    int row = i / KZX, k = i - row*KZX;
    float v = (row < G3) ? W_ih[(size_t)row*INd + k] : W_dh[(size_t)(row-G3)*KZX + k];
    g_wh[i] = __float2half(v);
}

// -------- Phase 1: HMMA fp16 (A hi/lo fused, W preconverted), single sync ------
#define P1SM 52224
__global__ __launch_bounds__(512,1) void phase1f(
    const float* __restrict__ enc, const float* __restrict__ zin,
    const float* __restrict__ W_ih, const float* __restrict__ b_ih,
    const float* __restrict__ b_dh, const float* __restrict__ b_hh,
    const float* __restrict__ lobs, const float* __restrict__ sg)
{
    extern __shared__ __align__(1024) char sm[];
    uint32_t sb=s2u(sm);
    const uint32_t oAh=0, oAl=12288, oBh=24576;
    float* colb=(float*)(sm+49152); float* c58=(float*)(sm+50176); float* c59=(float*)(sm+51200);
    int tid=threadIdx.x, lane=tid&31, w=tid>>5;
    int wm=w>>3, wn=w&7;
    int m0=blockIdx.y*128, n0=blockIdx.x*256;

    if(tid<256){
        int j=n0+tid; float cb,w58=0.f,w59=0.f;
        if(j<G3){ cb=b_ih[j]+((j<256)?b_hh[j]:0.f);
                  w58=W_ih[(size_t)j*INd+1058]; w59=W_ih[(size_t)j*INd+1059]; }
        else cb=b_dh[j-G3];
        colb[tid]=cb; c58[tid]=w58; c59[tid]=w59;
    }

    int ra=tid>>2, kq=(tid&3)*4;
    int ma=m0+ra;
    const float* ae=enc+(size_t)ma*1024; const float* az=zin+(size_t)ma*32;
    const __half* bp0h=g_wh+(size_t)(n0+ra)*KZX;
    const __half* bp1h=bp0h+(size_t)128*KZX;

    float acc[4][4][4];
    #pragma unroll
    for(int i=0;i<4;i++)
        #pragma unroll
        for(int j2=0;j2<4;j2++){ acc[i][j2][0]=0.f; acc[i][j2][1]=0.f; acc[i][j2][2]=0.f; acc[i][j2][3]=0.f; }

#define LDT(kt) { int kk=(kt)*16+kq; \
    av=(kk<1024)?*(const float4*)(ae+kk):*(const float4*)(az+(kk-1024)); \
    bh0=*(const uint2*)(bp0h+kk); bh1=*(const uint2*)(bp1h+kk); }
#define STT(bf) { \
    uint32_t _off=(bf)*6144+ra*48+(tid&3)*8; \
    uint32_t _h0=pkhf(av.x,av.y), _h1=pkhf(av.z,av.w); \
    float _rx=av.x-hlo(_h0), _ry=av.y-hhi(_h0), _rz=av.z-hlo(_h1), _rw=av.w-hhi(_h1); \
    *(uint2*)(sm+oAh+_off)=make_uint2(_h0,_h1); \
    *(uint2*)(sm+oAl+_off)=make_uint2(pkhf(_rx,_ry),pkhf(_rz,_rw)); \
    *(uint2*)(sm+oBh+(bf)*12288+ra*48+(tid&3)*8)=bh0; \
    *(uint2*)(sm+oBh+(bf)*12288+(ra+128)*48+(tid&3)*8)=bh1; }

    float4 av; uint2 bh0,bh1;
    LDT(0); STT(0);
    __syncthreads();

    for(int kt=0;kt<66;kt++){
        int buf=kt&1;
        if(kt<65) LDT(kt+1);
        uint32_t aBh=sb+oAh+buf*6144+(uint32_t)((wm*64+(lane&15))*48+(lane>>4)*16);
        uint32_t aBl=aBh+(oAl-oAh);
        uint32_t bOff=(uint32_t)((wn*32+(lane>>4)*8+(lane&7))*48+((lane>>3)&1)*16);
        uint32_t bBh=sb+oBh+buf*12288+bOff;
        uint32_t Bh0[4],Bh1[4];
        ldsm4(Bh0,bBh); ldsm4(Bh1,bBh+16*48);
        #pragma unroll
        for(int mt=0;mt<4;mt++){
            uint32_t Af[4],Alf[4];
            ldsm4(Af, aBh+(uint32_t)(mt*16*48));
            ldsm4(Alf,aBl+(uint32_t)(mt*16*48));
            #pragma unroll
            for(int nt=0;nt<4;nt++){
                uint32_t b0=(nt<2?Bh0:Bh1)[(nt&1)*2], b1=(nt<2?Bh0:Bh1)[(nt&1)*2+1];
                mmahf(acc[mt][nt],Af,b0,b1);
                mmahf(acc[mt][nt],Alf,b0,b1);
            }
        }
        if(kt<65){ int nb=(kt+1)&1; STT(nb); }
        __syncthreads();
    }

    const float idt=1.f/4.8f;
    #pragma unroll
    for(int mt=0;mt<4;mt++){
        #pragma unroll
        for(int h=0;h<2;h++){
            int m=m0+wm*64+mt*16+(lane>>2)+8*h;
            float r0=(sg[2*m]-lobs[6*m])*idt, r1=(sg[2*m+1]-lobs[6*m+1])*idt;
            #pragma unroll
            for(int nt=0;nt<4;nt++){
                int jl=wn*32+nt*8+2*(lane&3);
                float vx=acc[mt][nt][2*h]  +colb[jl]  +r0*c58[jl]  +r1*c59[jl];
                float vy=acc[mt][nt][2*h+1]+colb[jl+1]+r0*c58[jl+1]+r1*c59[jl+1];
                *(float2*)&g_sc[(size_t)m*NC+n0+jl]=make_float2(vx,vy);
            }
        }
    }
#undef LDT
#undef STT
}

// -------- Phase 2: phase2r + gi staged in smem as fp16 (XOR-swizzled) --------
// smem: WHs fp16[384*136] @0 (104448), gis u32[112][192] @104448 (86016),
//       hx u32[112][68] @190464 (30464), px @220928 (3584), was @224512 (3072),
//       wm4 @227584 (2048), bh2 @229632 (512). total 230144.
#define SM2U 230144
__global__ __launch_bounds__(448,1) void phase2u(
    const float* __restrict__ W_hh, const float* __restrict__ W_ih,
    const float* __restrict__ b_hh,
    const float* __restrict__ W_mu, const float* __restrict__ b_mu,
    const float* __restrict__ W_std, const float* __restrict__ b_std,
    const float* __restrict__ lobs, const float* __restrict__ W_vel,
    const float* __restrict__ b_vel, const float* __restrict__ fut,
    float* __restrict__ out)
{
    extern __shared__ __align__(1024) char sm[];
    __half* WHs=(__half*)sm;
    uint32_t* gis=(uint32_t*)(sm+104448);
    uint32_t* hx=(uint32_t*)(sm+190464);
    float2* px=(float2*)(sm+220928);
    float2* was=(float2*)(sm+224512);
    float4* wm4=(float4*)(sm+227584);
    float2* bh2=(float2*)(sm+229632);
    int tid=threadIdx.x, lane=tid&31, wid=tid>>5;
    int pair=wid>>1, half=wid&1;
    int q=lane&3, rq=lane>>2;
    int rbb=blockIdx.x*112;
    int rb=rbb+pair*16;
    int row0=rb+rq, row1=row0+8;
    bool active=rb<Bn;

    for(int i=tid;i<G3*128;i+=448){
        int n=i>>7,k=i&127;
        WHs[n*WS+k]=__float2half(W_hh[i]);
    }
    // stage gi (cols 0..383) as fp16 pairs, XOR swizzle (j ^ (row&7)*4)
    for(int p=tid;p<112*192;p+=448){
        int row=p/192, j=p-row*192;
        if(rbb+row<Bn){
            float2 v=*(const float2*)&g_sc[(size_t)(rbb+row)*NC+2*j];
            gis[row*192+(j^((row&7)*4))]=pkhf(v.x,v.y);
        }
    }
    for(int i=tid;i<G3;i+=448)
        was[i]=make_float2(W_ih[(size_t)i*INd+1056],W_ih[(size_t)i*INd+1057]);
    if(tid<128) wm4[tid]=make_float4(W_mu[tid],W_mu[128+tid],W_std[tid],W_std[128+tid]);
    if(tid<64)  bh2[tid]=make_float2(b_hh[256+2*tid],b_hh[257+2*tid]);
    __syncthreads();
    if(!active) return;

    uint32_t sWH=s2u(WHs);
    uint32_t boff=(uint32_t)(((lane&7)*WS+(lane>>3)*8)*2);
    uint32_t hb=(uint32_t)(pair*1088);
    int rrel0=pair*16+rq;       // row0 - rbb
    int rrel1=rrel0+8;

    uint32_t Ah[8][4];
    float hp[32];
    #pragma unroll
    for(int kt=0;kt<8;kt++){
        #pragma unroll
        for(int rg=0;rg<4;rg++){
            int r=(rg&1)?row1:row0;
            int cb=kt*16+((rg>>1)*8)+2*q;
            float2 v=*(const float2*)&g_sc[(size_t)r*NC+G3+cb];
            Ah[kt][rg]=pkhf(v.x,v.y);
        }
    }
    #pragma unroll
    for(int c2=0;c2<8;c2++){
        int cg=half*8+c2;
        float2 v0=*(const float2*)&g_sc[(size_t)row0*NC+G3+8*cg+2*q];
        float2 v1=*(const float2*)&g_sc[(size_t)row1*NC+G3+8*cg+2*q];
        hp[c2*4+0]=v0.x; hp[c2*4+1]=v0.y;
        hp[c2*4+2]=v1.x; hp[c2*4+3]=v1.y;
    }
    float2 a0r0,a0r1;
    { float s0=b_vel[0],s1=b_vel[1],t0=s0,t1=s1;
      #pragma unroll
      for(int k=0;k<6;k++){
          float v0=__ldg(&lobs[row0*6+k]), v1=__ldg(&lobs[row1*6+k]);
          s0=fmaf(v0,W_vel[k],s0); s1=fmaf(v0,W_vel[6+k],s1);
          t0=fmaf(v1,W_vel[k],t0); t1=fmaf(v1,W_vel[6+k],t1); }
      a0r0=make_float2(s0,s1); a0r1=make_float2(t0,t1); }
    float bm0=b_mu[0],bm1=b_mu[1],bs0=b_std[0],bs1=b_std[1];

    for(int t=0;t<Tn;t++){
        float2 aR0,aR1;
        if(t==0){ aR0=a0r0; aR1=a0r1; }
        else { aR0=*(const float2*)&fut[((size_t)(t-1)*Bn+row0)*6+2];
               aR1=*(const float2*)&fut[((size_t)(t-1)*Bn+row1)*6+2]; }
        float p0=0,p1=0,p2=0,p3=0,p4=0,p5=0,p6=0,p7=0;
        #pragma unroll
        for(int c2=0;c2<8;c2++){
            int cg=half*8+c2;
            float cr[4]={0,0,0,0}, cz[4]={0,0,0,0}, cn[4]={0,0,0,0};
            #pragma unroll
            for(int k2=0;k2<4;k2++){
                uint32_t ab=(uint32_t)(((8*cg)*WS+k2*32)*2)+boff;
                uint32_t br[4],bz[4],bn[4];
                ldsm4(br, sWH+ab);
                ldsm4(bz, sWH+ab+128*WS*2);
                ldsm4(bn, sWH+ab+256*WS*2);
                #pragma unroll
                for(int h2=0;h2<2;h2++){
                    int kt=2*k2+h2;
                    mmahf(cr,Ah[kt],br[2*h2],br[2*h2+1]);
                    mmahf(cz,Ah[kt],bz[2*h2],bz[2*h2+1]);
                    mmahf(cn,Ah[kt],bn[2*h2],bn[2*h2+1]);
                }
            }
            // gi from swizzled smem: word j = gate*64 + cg*4 + q, XOR rq*4
            int jx=(cg*4+q)^(rq*4);
            int w0=rrel0*192+jx, w1=rrel1*192+jx;
            uint32_t ur0=gis[w0],     uz0=gis[w0+64],  un0=gis[w0+128];
            uint32_t ur1=gis[w1],     uz1=gis[w1+64],  un1=gis[w1+128];
            float4 wr=*(const float4*)&was[8*cg+2*q];
            float4 wz=*(const float4*)&was[128+8*cg+2*q];
            float4 wn=*(const float4*)&was[256+8*cg+2*q];
            float2 bh=bh2[4*cg+q];
            float4 w0v=wm4[8*cg+2*q], w1v=wm4[8*cg+2*q+1];
            float r0x=sigf(hlo(ur0)+aR0.x*wr.x+aR0.y*wr.y+cr[0]);
            float r0y=sigf(hhi(ur0)+aR0.x*wr.z+aR0.y*wr.w+cr[1]);
            float r1x=sigf(hlo(ur1)+aR1.x*wr.x+aR1.y*wr.y+cr[2]);
            float r1y=sigf(hhi(ur1)+aR1.x*wr.z+aR1.y*wr.w+cr[3]);
            float z0x=sigf(hlo(uz0)+aR0.x*wz.x+aR0.y*wz.y+cz[0]);
            float z0y=sigf(hhi(uz0)+aR0.x*wz.z+aR0.y*wz.w+cz[1]);
            float z1x=sigf(hlo(uz1)+aR1.x*wz.x+aR1.y*wz.y+cz[2]);
            float z1y=sigf(hhi(uz1)+aR1.x*wz.z+aR1.y*wz.w+cz[3]);
            float n0x=tanha(hlo(un0)+aR0.x*wn.x+aR0.y*wn.y+r0x*(cn[0]+bh.x));
            float n0y=tanha(hhi(un0)+aR0.x*wn.z+aR0.y*wn.w+r0y*(cn[1]+bh.y));
            float n1x=tanha(hlo(un1)+aR1.x*wn.x+aR1.y*wn.y+r1x*(cn[2]+bh.x));
            float n1y=tanha(hhi(un1)+aR1.x*wn.z+aR1.y*wn.w+r1y*(cn[3]+bh.y));
            float h0x=(1.f-z0x)*n0x+z0x*hp[c2*4+0];
            float h0y=(1.f-z0y)*n0y+z0y*hp[c2*4+1];
            float h1x=(1.f-z1x)*n1x+z1x*hp[c2*4+2];
            float h1y=(1.f-z1y)*n1y+z1y*hp[c2*4+3];
            hp[c2*4+0]=h0x; hp[c2*4+1]=h0y;
            hp[c2*4+2]=h1x; hp[c2*4+3]=h1y;
            p0=fmaf(h0x,w0v.x,p0); p0=fmaf(h0y,w1v.x,p0);
            p1=fmaf(h0x,w0v.y,p1); p1=fmaf(h0y,w1v.y,p1);
            p2=fmaf(h0x,w0v.z,p2); p2=fmaf(h0y,w1v.z,p2);
            p3=fmaf(h0x,w0v.w,p3); p3=fmaf(h0y,w1v.w,p3);
            p4=fmaf(h1x,w0v.x,p4); p4=fmaf(h1y,w1v.x,p4);
            p5=fmaf(h1x,w0v.y,p5); p5=fmaf(h1y,w1v.y,p5);
            p6=fmaf(h1x,w0v.z,p6); p6=fmaf(h1y,w1v.z,p6);
            p7=fmaf(h1x,w0v.w,p7); p7=fmaf(h1y,w1v.w,p7);
            uint32_t wofs=hb+(uint32_t)(cg*4+q);
            hx[wofs+rq*68]    =pkhf(h0x,h0y);
            hx[wofs+(rq+8)*68]=pkhf(h1x,h1y);
        }
        p0+=__shfl_xor_sync(~0u,p0,1); p0+=__shfl_xor_sync(~0u,p0,2);
        p1+=__shfl_xor_sync(~0u,p1,1); p1+=__shfl_xor_sync(~0u,p1,2);
        p2+=__shfl_xor_sync(~0u,p2,1); p2+=__shfl_xor_sync(~0u,p2,2);
        p3+=__shfl_xor_sync(~0u,p3,1); p3+=__shfl_xor_sync(~0u,p3,2);
        p4+=__shfl_xor_sync(~0u,p4,1); p4+=__shfl_xor_sync(~0u,p4,2);
        p5+=__shfl_xor_sync(~0u,p5,1); p5+=__shfl_xor_sync(~0u,p5,2);
        p6+=__shfl_xor_sync(~0u,p6,1); p6+=__shfl_xor_sync(~0u,p6,2);
        p7+=__shfl_xor_sync(~0u,p7,1); p7+=__shfl_xor_sync(~0u,p7,2);
        float2 mine;
        if(q<2) mine=make_float2((q&1)?p4:p0,(q&1)?p5:p1);
        else    mine=make_float2((q&1)?p6:p2,(q&1)?p7:p3);
        px[pair*64+half*32+lane]=mine;
        asm volatile("bar.sync %0,64;"::"r"(pair+1):"memory");
        #pragma unroll
        for(int kt=0;kt<8;kt++){
            #pragma unroll
            for(int ch=0;ch<2;ch++){
                uint32_t pw=hb+(uint32_t)((2*kt+ch)*4+q);
                Ah[kt][ch*2  ]=hx[pw+rq*68];
                Ah[kt][ch*2+1]=hx[pw+(rq+8)*68];
            }
        }
        if(half==0){
            float2 other=px[pair*64+32+lane];
            float vx=mine.x+other.x, vy=mine.y+other.y;
            int orow=(q&1)?row1:row0;
            if(q<2)
                *(float2*)&out[(size_t)t*Bn*2+(size_t)orow*2]=make_float2(vx+bm0,vy+bm1);
            else
                *(float2*)&out[(size_t)(Tn+t)*Bn*2+(size_t)orow*2]=
                    make_float2(__expf(0.5f*(vx+bs0)),__expf(0.5f*(vy+bs1)));
        }
        asm volatile("bar.sync %0,64;"::"r"(pair+1):"memory");
    }
}

extern "C" void kernel_launch(void* const* d_in, const int* in_sizes, int n_in,
                              void* d_out, int out_size) {
    const float* lobs=(const float*)d_in[0];
    const float* enc =(const float*)d_in[1];
    const float* zin =(const float*)d_in[2];
    const float* sg  =(const float*)d_in[3];
    const float* fut =(const float*)d_in[4];
    const float* W_dh=(const float*)d_in[5];
    const float* b_dh=(const float*)d_in[6];
    const float* W_vel=(const float*)d_in[7];
    const float* b_vel=(const float*)d_in[8];
    const float* W_ih=(const float*)d_in[9];
    const float* b_ih=(const float*)d_in[10];
    const float* W_hh=(const float*)d_in[11];
    const float* b_hh=(const float*)d_in[12];
    const float* W_mu=(const float*)d_in[13];
    const float* b_mu=(const float*)d_in[14];
    const float* W_std=(const float*)d_in[15];
    const float* b_std=(const float*)d_in[16];
    float* out=(float*)d_out;

    convW<<<(512*KZX+255)/256,256>>>(W_ih,W_dh);

    cudaFuncSetAttribute(phase1f, cudaFuncAttributeMaxDynamicSharedMemorySize, P1SM);
    phase1f<<<dim3(2,128),512,P1SM>>>(enc,zin,W_ih,b_ih,b_dh,b_hh,lobs,sg);

    cudaFuncSetAttribute(phase2u, cudaFuncAttributeMaxDynamicSharedMemorySize, SM2U);
    phase2u<<<147,448,SM2U>>>(W_hh,W_ih,b_hh,W_mu,b_mu,W_std,b_std,
                              lobs,W_vel,b_vel,fut,out);
}